// round 7
// baseline (speedup 1.0000x reference)
#include <cuda_runtime.h>
#include <cuda_bf16.h>
#include <cuda_pipeline.h>

// SRU PROJ forward:
//   g1  = sigmoid(u1 + bias)
//   cur = (cur - u0) * g1 + u0
// u: [L, B, D, 2] f32, bias: [D], init: [B, D]
// out: c: [L, B, D] (+ last: [B, D] appended if out_size allows).
//
// R6: cp.async (LDGSTS) pipeline with per-group FIFO completion.
// Register double-buffering was stuck at ~67% DRAM because SASS has only 6
// scoreboard slots: consuming an "old" load waits on a slot shared with
// just-issued prefetches (counting-SB max-of-arms) -> batch-synchronous,
// effective MLP ~8-16. cp.async groups complete strictly in order and
// __pipeline_wait_prior(D-1) waits ONLY for the oldest group, keeping a true
// DEPTH loads/thread in flight continuously.
// Launch: 147 blocks x 224 threads = 1 block/SM, balanced (the 512x64 launch
// had a 4-vs-3 blocks/SM imbalance -> ~16% tail).

#define DEPTH 24
#define TPB   224

__global__ __launch_bounds__(TPB, 1)
void sru_fwd_kernel(const float2* __restrict__ u,
                    const float*  __restrict__ bias,
                    const float*  __restrict__ init,
                    float*        __restrict__ c,
                    float*        __restrict__ last,
                    int L, int BD, int D)
{
    __shared__ float2 stage[DEPTH * TPB];   // [stage][thread], 43 KB

    const int tid = threadIdx.x;
    const int idx = blockIdx.x * TPB + tid;
    if (idx >= BD) return;

    const float bb = __ldg(&bias[idx % D]);
    float cur = init[idx];

    const float2* up = u + idx;   // stride BD float2 per timestep
    float*        cp = c + idx;   // stride BD floats per timestep

    float2* my = stage + tid;     // my slot s at my[s * TPB]

    // Prologue: issue DEPTH async copies, one commit group each.
    #pragma unroll
    for (int i = 0; i < DEPTH; ++i) {
        if (i < L)
            __pipeline_memcpy_async(&my[i * TPB], &up[i * BD], sizeof(float2));
        __pipeline_commit();
    }

    int slot = 0;
    for (int l = 0; l < L; ++l) {
        // Group l is the oldest; DEPTH-1 newer groups may remain in flight.
        __pipeline_wait_prior(DEPTH - 1);

        const float2 v = my[slot * TPB];

        // Refill this slot with timestep l + DEPTH (always commit to keep
        // group accounting uniform).
        const int j = l + DEPTH;
        if (j < L)
            __pipeline_memcpy_async(&my[slot * TPB], &up[j * BD], sizeof(float2));
        __pipeline_commit();

        const float g = __fdividef(1.0f, 1.0f + __expf(-(v.y + bb)));
        cur = fmaf(cur - v.x, g, v.x);
        __stcs(&cp[l * BD], cur);

        slot = (slot + 1 == DEPTH) ? 0 : slot + 1;
    }

    if (last) last[idx] = cur;
}

extern "C" void kernel_launch(void* const* d_in, const int* in_sizes, int n_in,
                              void* d_out, int out_size)
{
    const float2* u    = (const float2*)d_in[0];
    const float*  bias = (const float*) d_in[1];
    const float*  init = (const float*) d_in[2];

    const int D  = in_sizes[1];            // 1024
    const int BD = in_sizes[2];            // B * D = 32768
    const int L  = in_sizes[0] / (BD * 2); // 1024

    float* c = (float*)d_out;
    float* last = nullptr;
    const long long c_elems = (long long)L * (long long)BD;
    if ((long long)out_size >= c_elems + BD) {
        last = c + c_elems;
    }

    const int blocks = (BD + TPB - 1) / TPB;   // 147 -> one block per SM
    sru_fwd_kernel<<<blocks, TPB>>>(u, bias, init, c, last, L, BD, D);
}

// round 9
// speedup vs baseline: 1.0298x; 1.0298x over previous
#include <cuda_runtime.h>
#include <cuda_bf16.h>
#include <cstdint>

// SRU PROJ forward:
//   g1  = sigmoid(u1 + bias)
//   cur = (cur - u0) * g1 + u0
// u: [L, B, D, 2] f32, bias: [D], init: [B, D]
// out: c: [L, B, D] (+ last: [B, D] appended).
//
// R7: cp.async.bulk (TMA/UBLKCP) pipeline. Each block owns 256 contiguous
// (b,d) columns, so one timestep = one contiguous 2KB slab in gmem. A 7-stage
// ring of 16KB stages (8 timesteps each) is filled with 1D bulk copies whose
// completion is mbarrier transaction-counted: precise FIFO completion, no
// LDG scoreboard aliasing (the thing that pinned every register-pipeline
// variant at ~67% DRAM), ~98KB/SM in flight. Consumers LDS + compute + STG.

#define TPB   256
#define TILE  8            // timesteps per stage
#define NST   7            // ring stages
#define ROWB  (TPB * 8)    // bytes per timestep slab per block = 2048

__device__ __forceinline__ uint32_t smem_u32(const void* p) {
    uint32_t a;
    asm("{ .reg .u64 t; cvta.to.shared.u64 t, %1; cvt.u32.u64 %0, t; }"
        : "=r"(a) : "l"(p));
    return a;
}

__global__ __launch_bounds__(TPB, 1)
void sru_fwd_kernel(const float2* __restrict__ u,
                    const float*  __restrict__ bias,
                    const float*  __restrict__ init,
                    float*        __restrict__ c,
                    float*        __restrict__ last,
                    int L, int BD, int D)
{
    extern __shared__ char smem[];
    // layout: stages [NST][TILE][TPB] float2, then mbarriers [NST]
    float2*   stage = (float2*)smem;
    uint64_t* mbar  = (uint64_t*)(smem + NST * TILE * ROWB);

    const int tid  = threadIdx.x;
    const int col0 = blockIdx.x * TPB;          // first column of this block
    const int idx  = col0 + tid;

    const uint32_t mbar_base = smem_u32(mbar);
    const uint32_t stage_base = smem_u32(stage);

    if (tid < NST) {
        asm volatile("mbarrier.init.shared.b64 [%0], %1;"
                     :: "r"(mbar_base + tid * 8), "r"(1) : "memory");
    }
    __syncthreads();

    const float bb  = __ldg(&bias[idx % D]);
    float cur = (idx < BD) ? init[idx] : 0.0f;

    const float2* ub = u + col0;      // row l at ub + l*BD
    float*        cp = c + idx;

    const int ntiles = L / TILE;      // L=1024, TILE=8 -> 128 (assume divisible)

    // Producer: issue tile t into slot s (single thread).
    auto produce = [&](int t, int s) {
        const uint32_t mb = mbar_base + s * 8;
        asm volatile("mbarrier.arrive.expect_tx.shared.b64 _, [%0], %1;"
                     :: "r"(mb), "r"((uint32_t)(TILE * ROWB)) : "memory");
        #pragma unroll
        for (int r = 0; r < TILE; ++r) {
            const uint32_t dst = stage_base + (uint32_t)((s * TILE + r) * ROWB);
            const float2*  src = ub + (size_t)(t * TILE + r) * BD;
            asm volatile(
                "cp.async.bulk.shared::cta.global.mbarrier::complete_tx::bytes "
                "[%0], [%1], %2, [%3];"
                :: "r"(dst), "l"(src), "r"((uint32_t)ROWB), "r"(mb) : "memory");
        }
    };

    // Prologue: fill the ring.
    if (tid == 0) {
        for (int t = 0; t < NST && t < ntiles; ++t) produce(t, t);
    }

    for (int t = 0; t < ntiles; ++t) {
        const int s  = t % NST;
        const int ph = (t / NST) & 1;
        const uint32_t mb = mbar_base + s * 8;

        // Wait for stage full (acquire orders TMA writes before our LDS).
        {
            uint32_t done;
            asm volatile(
                "{\n\t.reg .pred p;\n\t"
                "mbarrier.try_wait.parity.acquire.cta.shared::cta.b64 p, [%1], %2;\n\t"
                "selp.b32 %0, 1, 0, p;\n\t}"
                : "=r"(done) : "r"(mb), "r"((uint32_t)ph) : "memory");
            if (!done) {
                asm volatile(
                    "{\n\t.reg .pred P1;\n\t"
                    "W_%=:\n\t"
                    "mbarrier.try_wait.parity.acquire.cta.shared::cta.b64 P1, [%0], %1, 0x989680;\n\t"
                    "@P1 bra.uni D_%=;\n\t"
                    "bra.uni W_%=;\n\t"
                    "D_%=:\n\t}"
                    :: "r"(mb), "r"((uint32_t)ph) : "memory");
            }
        }

        const float2* myrow = stage + s * TILE * TPB + tid;
        const int lbase = t * TILE;
        #pragma unroll
        for (int r = 0; r < TILE; ++r) {
            const float2 v = myrow[r * TPB];
            const float g = __fdividef(1.0f, 1.0f + __expf(-(v.y + bb)));
            cur = fmaf(cur - v.x, g, v.x);
            if (idx < BD) __stcs(&cp[(lbase + r) * BD], cur);
        }

        __syncthreads();   // everyone done reading slot s
        if (tid == 0 && t + NST < ntiles) produce(t + NST, s);
    }

    // Tail (L not divisible by TILE) — plain loads.
    for (int l = ntiles * TILE; l < L; ++l) {
        const float2 v = __ldcs(&u[(size_t)l * BD + idx]);
        const float g = __fdividef(1.0f, 1.0f + __expf(-(v.y + bb)));
        cur = fmaf(cur - v.x, g, v.x);
        if (idx < BD) __stcs(&cp[l * BD], cur);
    }

    if (last && idx < BD) last[idx] = cur;
}

extern "C" void kernel_launch(void* const* d_in, const int* in_sizes, int n_in,
                              void* d_out, int out_size)
{
    const float2* u    = (const float2*)d_in[0];
    const float*  bias = (const float*) d_in[1];
    const float*  init = (const float*) d_in[2];

    const int D  = in_sizes[1];            // 1024
    const int BD = in_sizes[2];            // B * D = 32768
    const int L  = in_sizes[0] / (BD * 2); // 1024

    float* c = (float*)d_out;
    float* last = nullptr;
    const long long c_elems = (long long)L * (long long)BD;
    if ((long long)out_size >= c_elems + BD) {
        last = c + c_elems;
    }

    const int smem_bytes = NST * TILE * ROWB + NST * 8 + 16;  // ~114.7 KB
    cudaFuncSetAttribute(sru_fwd_kernel,
                         cudaFuncAttributeMaxDynamicSharedMemorySize, smem_bytes);

    const int blocks = (BD + TPB - 1) / TPB;   // 128
    sru_fwd_kernel<<<blocks, TPB, smem_bytes>>>(u, bias, init, c, last, L, BD, D);
}

// round 11
// speedup vs baseline: 1.3135x; 1.2755x over previous
#include <cuda_runtime.h>
#include <cuda_bf16.h>

// SRU PROJ forward:
//   g1  = sigmoid(u1 + bias)
//   cur = (cur - u0) * g1 + u0
// u: [L, B, D, 2] f32, bias: [D], init: [B, D]
// out: c: [L, B, D] (+ last: [B, D] appended).
//
// R9: R4's ping-pong register pipeline (best so far, 70.4us / 68% DRAM) but
// 2 columns per thread with float4 loads and float2 stores. Evidence from
// R4-R7: DRAM% is pinned at ~67-68% independent of MLP depth, SM coverage,
// and load path (LDG vs TMA) -> limiter is request granularity / burst
// efficiency, not parallelism. LDG.128 (512B/warp, 4 lines) + STG.64
// (256B/warp) halves instruction and L1tex-wavefront count per byte while
// keeping 256B/thread in flight (16 x float4).

#define SRU_BATCH 16
#define TPB 128

__global__ __launch_bounds__(TPB, 1)
void sru_fwd_kernel(const float4* __restrict__ u4,   // u as float4: 2 cols/elem
                    const float*  __restrict__ bias,
                    const float2* __restrict__ init2,
                    float2*       __restrict__ c2,   // c as float2: 2 cols/elem
                    float2*       __restrict__ last2,
                    int L, int BD2, int D2)          // BD2 = B*D/2, D2 = D/2
{
    const int idx = blockIdx.x * TPB + threadIdx.x;  // pair index
    if (idx >= BD2) return;

    const int dpair = idx % D2;                 // pair index within D
    const float b0 = __ldg(&bias[2 * dpair]);
    const float b1 = __ldg(&bias[2 * dpair + 1]);

    float2 ini = init2[idx];
    float cur0 = ini.x, cur1 = ini.y;

    const float4* up = u4 + idx;   // stride BD2 float4 per timestep
    float2*       cp = c2 + idx;   // stride BD2 float2 per timestep

    float4 bufA[SRU_BATCH];
    float4 bufB[SRU_BATCH];

    // Prologue: fill buffer A with batch 0.
    #pragma unroll
    for (int i = 0; i < SRU_BATCH; ++i)
        bufA[i] = __ldcs(&up[i * BD2]);

    for (int base = 0; base < L; base += 2 * SRU_BATCH) {
        const int nb1 = base + SRU_BATCH;
        if (nb1 < L) {
            #pragma unroll
            for (int i = 0; i < SRU_BATCH; ++i)
                bufB[i] = __ldcs(&up[(nb1 + i) * BD2]);
        }
        #pragma unroll
        for (int i = 0; i < SRU_BATCH; ++i) {
            const float4 v = bufA[i];
            const float g0 = __fdividef(1.0f, 1.0f + __expf(-(v.y + b0)));
            const float g1 = __fdividef(1.0f, 1.0f + __expf(-(v.w + b1)));
            cur0 = fmaf(cur0 - v.x, g0, v.x);
            cur1 = fmaf(cur1 - v.z, g1, v.z);
            __stcs(&cp[(base + i) * BD2], make_float2(cur0, cur1));
        }

        const int nb2 = base + 2 * SRU_BATCH;
        if (nb2 < L) {
            #pragma unroll
            for (int i = 0; i < SRU_BATCH; ++i)
                bufA[i] = __ldcs(&up[(nb2 + i) * BD2]);
        }
        if (nb1 < L) {
            #pragma unroll
            for (int i = 0; i < SRU_BATCH; ++i) {
                const float4 v = bufB[i];
                const float g0 = __fdividef(1.0f, 1.0f + __expf(-(v.y + b0)));
                const float g1 = __fdividef(1.0f, 1.0f + __expf(-(v.w + b1)));
                cur0 = fmaf(cur0 - v.x, g0, v.x);
                cur1 = fmaf(cur1 - v.z, g1, v.z);
                __stcs(&cp[(nb1 + i) * BD2], make_float2(cur0, cur1));
            }
        }
    }

    if (last2) last2[idx] = make_float2(cur0, cur1);
}

extern "C" void kernel_launch(void* const* d_in, const int* in_sizes, int n_in,
                              void* d_out, int out_size)
{
    const float4* u4    = (const float4*)d_in[0];
    const float*  bias  = (const float*) d_in[1];
    const float2* init2 = (const float2*)d_in[2];

    const int D   = in_sizes[1];            // 1024
    const int BD  = in_sizes[2];            // B * D = 32768
    const int L   = in_sizes[0] / (BD * 2); // 1024
    const int BD2 = BD / 2;                 // 16384
    const int D2  = D / 2;

    float2* c2 = (float2*)d_out;
    float2* last2 = nullptr;
    const long long c_elems = (long long)L * (long long)BD;
    if ((long long)out_size >= c_elems + BD) {
        last2 = (float2*)((float*)d_out + c_elems);
    }

    const int blocks = (BD2 + TPB - 1) / TPB;   // 128
    sru_fwd_kernel<<<blocks, TPB>>>(u4, bias, init2, c2, last2, L, BD2, D2);
}

// round 13
// speedup vs baseline: 1.5185x; 1.1561x over previous
#include <cuda_runtime.h>
#include <cuda_bf16.h>
#include <cuda_pipeline.h>

// SRU PROJ forward:
//   g1  = sigmoid(u1 + bias)
//   cur = (cur - u0) * g1 + u0
// u: [L, B, D, 2] f32, bias: [D], init: [B, D]
// out: c: [L, B, D] (+ last: [B, D] appended).
//
// R11: per-thread cp.async.cg (16B) pipeline, 2 columns/thread, one commit
// group per GSTEPS=4 timesteps, NGRP=8 groups rolling.
// Why: every register-buffer variant averages only ~half its nominal
// in-flight bytes (batch-synchronous drain / 6-scoreboard-slot aliasing),
// which quantitatively predicts the measured 5.4TB/s (need ~3.2MB chip-wide
// in flight, averaged ~2.1MB). __pipeline_wait_prior gives precise FIFO
// completion: waiting for the oldest group leaves 7 newer groups (28 steps x
// 16B/thread ~ 7MB chip) continuously in flight. R6 proved FIFO works but
// drowned in per-element commit bookkeeping; grouping by 4 steps cuts that
// 8x and 16B ops (cg) halve op count. No block-level sync (state is
// per-thread).

#define TPB    128
#define GSTEPS 4                     // timesteps per commit group
#define NGRP   8                     // rolling groups
#define STEPS  (GSTEPS * NGRP)       // 32 staged timesteps

__global__ __launch_bounds__(TPB, 1)
void sru_fwd_kernel(const float4* __restrict__ u4,   // 2 cols per float4
                    const float*  __restrict__ bias,
                    const float2* __restrict__ init2,
                    float2*       __restrict__ c2,
                    float2*       __restrict__ last2,
                    int L, int BD2, int D2)
{
    __shared__ float4 stage[STEPS][TPB];   // 64 KB

    const int tid = threadIdx.x;
    const int idx = blockIdx.x * TPB + tid;   // column-pair index
    if (idx >= BD2) return;

    const int dpair = idx % D2;
    const float b0 = __ldg(&bias[2 * dpair]);
    const float b1 = __ldg(&bias[2 * dpair + 1]);

    const float2 ini = init2[idx];
    float cur0 = ini.x, cur1 = ini.y;

    const float4* up = u4 + idx;   // stride BD2 float4 per timestep
    float2*       cp = c2 + idx;   // stride BD2 float2 per timestep

    const int ngroups = L / GSTEPS;          // 256 for L=1024

    // Prologue: issue NGRP groups.
    #pragma unroll
    for (int g = 0; g < NGRP; ++g) {
        #pragma unroll
        for (int s = 0; s < GSTEPS; ++s) {
            const int l = g * GSTEPS + s;
            if (l < L)
                __pipeline_memcpy_async(&stage[g * GSTEPS + s][tid],
                                        &up[(size_t)l * BD2], sizeof(float4));
        }
        __pipeline_commit();
    }

    // Main loop: outer strides of NGRP keep slot indices compile-time.
    for (int ob = 0; ob < ngroups; ob += NGRP) {
        #pragma unroll
        for (int g = 0; g < NGRP; ++g) {
            const int grp = ob + g;

            // Wait for the oldest group (this one); 7 newer stay in flight.
            __pipeline_wait_prior(NGRP - 1);

            // Read the 4 staged timesteps into registers first.
            float4 v[GSTEPS];
            #pragma unroll
            for (int s = 0; s < GSTEPS; ++s)
                v[s] = stage[g * GSTEPS + s][tid];

            // Refill this group's slots with timesteps NGRP groups ahead.
            const int nt = grp + NGRP;
            if (nt < ngroups) {
                #pragma unroll
                for (int s = 0; s < GSTEPS; ++s)
                    __pipeline_memcpy_async(&stage[g * GSTEPS + s][tid],
                                            &up[(size_t)(nt * GSTEPS + s) * BD2],
                                            sizeof(float4));
            }
            __pipeline_commit();   // always, to keep group accounting uniform

            // Compute + stream the 4 timesteps.
            const int lbase = grp * GSTEPS;
            #pragma unroll
            for (int s = 0; s < GSTEPS; ++s) {
                const float4 w = v[s];
                const float g0 = __fdividef(1.0f, 1.0f + __expf(-(w.y + b0)));
                const float g1 = __fdividef(1.0f, 1.0f + __expf(-(w.w + b1)));
                cur0 = fmaf(cur0 - w.x, g0, w.x);
                cur1 = fmaf(cur1 - w.z, g1, w.z);
                __stcs(&cp[(size_t)(lbase + s) * BD2], make_float2(cur0, cur1));
            }
        }
    }

    // Generic tail if L not divisible by GSTEPS (not hit for L=1024).
    for (int l = ngroups * GSTEPS; l < L; ++l) {
        const float4 w = __ldcs(&up[(size_t)l * BD2]);
        const float g0 = __fdividef(1.0f, 1.0f + __expf(-(w.y + b0)));
        const float g1 = __fdividef(1.0f, 1.0f + __expf(-(w.w + b1)));
        cur0 = fmaf(cur0 - w.x, g0, w.x);
        cur1 = fmaf(cur1 - w.z, g1, w.z);
        __stcs(&cp[(size_t)l * BD2], make_float2(cur0, cur1));
    }

    if (last2) last2[idx] = make_float2(cur0, cur1);
}

extern "C" void kernel_launch(void* const* d_in, const int* in_sizes, int n_in,
                              void* d_out, int out_size)
{
    const float4* u4    = (const float4*)d_in[0];
    const float*  bias  = (const float*) d_in[1];
    const float2* init2 = (const float2*)d_in[2];

    const int D   = in_sizes[1];            // 1024
    const int BD  = in_sizes[2];            // B * D = 32768
    const int L   = in_sizes[0] / (BD * 2); // 1024
    const int BD2 = BD / 2;                 // 16384
    const int D2  = D / 2;

    float2* c2 = (float2*)d_out;
    float2* last2 = nullptr;
    const long long c_elems = (long long)L * (long long)BD;
    if ((long long)out_size >= c_elems + BD) {
        last2 = (float2*)((float*)d_out + c_elems);
    }

    const int blocks = (BD2 + TPB - 1) / TPB;   // 128
    sru_fwd_kernel<<<blocks, TPB>>>(u4, bias, init2, c2, last2, L, BD2, D2);
}